// round 6
// baseline (speedup 1.0000x reference)
#include <cuda_runtime.h>
#include <cuda_bf16.h>
#include <stdint.h>
#include <math.h>

// ---------------------------------------------------------------- constants
#define BATCH   2
#define NQ      16384
#define NATOMS  1024
#define KDIM    256
#define ODIM    256
#define NROWS   (BATCH * NQ)
#define OMEGA0  30.0f
#define EPSD    1e-4f

#define BM      128
#define BN      128
#define BKC     16
#define NCHUNK  (KDIM / BKC)     // 16

#define PITCH   48               // bytes per 16-k row slice (conflict-free ldmatrix)
#define OFF_AH  0
#define OFF_AL  6144
#define OFF_BH  12288
#define OFF_BL  18432
#define STAGE   24576
#define NSTG    4
#define SM_BYTES (NSTG * STAGE)  // 98304
#define EPI_STRIDE 132           // floats (128*132*4 = 67584 <= OFF of stage 3)

// prep grid partition
#define XBLK    4096             // X split: 2,097,152 float4 / 512 per CTA
#define OBLK    512              // omega: 64 queries per CTA
#define WBLK    256              // W split: 256 elems per CTA

static __device__ __nv_bfloat16 g_Whi[ODIM * KDIM];
static __device__ __nv_bfloat16 g_Wlo[ODIM * KDIM];
static __device__ __nv_bfloat16 g_Xhi[NROWS * KDIM];
static __device__ __nv_bfloat16 g_Xlo[NROWS * KDIM];
static __device__ float         g_omega[NROWS];

// ---------------------------------------------------------------- helpers
__device__ __forceinline__ uint32_t smem_u32(const void* p) {
    uint32_t a;
    asm("{ .reg .u64 t; cvta.to.shared.u64 t, %1; cvt.u32.u64 %0, t; }" : "=r"(a) : "l"(p));
    return a;
}
__device__ __forceinline__ void cp16(uint32_t dst, const void* src) {
    asm volatile("cp.async.cg.shared.global [%0], [%1], 16;" :: "r"(dst), "l"(src));
}
#define CP_COMMIT() asm volatile("cp.async.commit_group;")
#define CP_WAIT2()  asm volatile("cp.async.wait_group 2;")

#define LDSM4(r, a) \
    asm volatile("ldmatrix.sync.aligned.m8n8.x4.shared.b16 {%0,%1,%2,%3}, [%4];" \
        : "=r"((r)[0]), "=r"((r)[1]), "=r"((r)[2]), "=r"((r)[3]) : "r"(a))

__device__ __forceinline__ void mma_bf16(float* c, const uint32_t* a,
                                         uint32_t b0, uint32_t b1) {
    asm volatile(
        "mma.sync.aligned.m16n8k16.row.col.f32.bf16.bf16.f32 "
        "{%0,%1,%2,%3}, {%4,%5,%6,%7}, {%8,%9}, {%0,%1,%2,%3};"
        : "+f"(c[0]), "+f"(c[1]), "+f"(c[2]), "+f"(c[3])
        : "r"(a[0]), "r"(a[1]), "r"(a[2]), "r"(a[3]), "r"(b0), "r"(b1));
}
__device__ __forceinline__ uint2 split4(float4 v, uint2& lo) {
    __nv_bfloat16 hx = __float2bfloat16(v.x), hy = __float2bfloat16(v.y);
    __nv_bfloat16 hz = __float2bfloat16(v.z), hw = __float2bfloat16(v.w);
    uint2 hi;
    hi.x = (uint32_t)__bfloat16_as_ushort(hx) | ((uint32_t)__bfloat16_as_ushort(hy) << 16);
    hi.y = (uint32_t)__bfloat16_as_ushort(hz) | ((uint32_t)__bfloat16_as_ushort(hw) << 16);
    __nv_bfloat16 lx = __float2bfloat16(v.x - __bfloat162float(hx));
    __nv_bfloat16 ly = __float2bfloat16(v.y - __bfloat162float(hy));
    __nv_bfloat16 lz = __float2bfloat16(v.z - __bfloat162float(hz));
    __nv_bfloat16 lw = __float2bfloat16(v.w - __bfloat162float(hw));
    lo.x = (uint32_t)__bfloat16_as_ushort(lx) | ((uint32_t)__bfloat16_as_ushort(ly) << 16);
    lo.y = (uint32_t)__bfloat16_as_ushort(lz) | ((uint32_t)__bfloat16_as_ushort(lw) << 16);
    return hi;
}

// ---------------------------------------------------------------- prep: X split + omega + W split
__global__ __launch_bounds__(256)
void prep_kernel(const float* __restrict__ X, const float* __restrict__ W,
                 const float* __restrict__ Q, const float* __restrict__ atoms,
                 const float* __restrict__ fw1, const float* __restrict__ fb1,
                 const float* __restrict__ fw2, const float* __restrict__ fb2)
{
    const int b = blockIdx.x, tid = threadIdx.x;

    if (b < XBLK) {
        // ---- X hi/lo split: 512 float4 per CTA ----
        const float4* Xv = (const float4*)X;
        uint2* Hv = (uint2*)g_Xhi;
        uint2* Lv = (uint2*)g_Xlo;
#pragma unroll
        for (int i = 0; i < 2; ++i) {
            int idx = b * 512 + tid + i * 256;
            uint2 lo;
            uint2 hi = split4(Xv[idx], lo);
            Hv[idx] = hi;
            Lv[idx] = lo;
        }
        return;
    }
    if (b < XBLK + OBLK) {
        // ---- omega: 64 queries per CTA, 4 threads per query ----
        __shared__ float4 sA[NATOMS];
        const int ob = b - XBLK;
        const int q0 = ob * 64;
        const int batch = (q0 >= NQ) ? 1 : 0;
        const float* ab = atoms + (size_t)batch * NATOMS * 3;
        for (int j = tid; j < NATOMS; j += 256) {
            float ax = ab[3*j], ay = ab[3*j+1], az = ab[3*j+2];
            sA[j] = make_float4(ax, ay, az, fmaf(ax, ax, fmaf(ay, ay, az*az)));
        }
        __syncthreads();

        const int qi = q0 + (tid >> 2);
        const int part = tid & 3;
        const float* qp = Q + (size_t)qi * 3;
        float qx = qp[0], qy = qp[1], qz = qp[2];
        float nqx = -2.f * qx, nqy = -2.f * qy, nqz = -2.f * qz;
        float md = 3.4e38f;
        const float4* at = sA + part * 256;
#pragma unroll 8
        for (int j = 0; j < 256; ++j) {
            float4 a = at[j];
            md = fminf(md, fmaf(a.x, nqx, fmaf(a.y, nqy, fmaf(a.z, nqz, a.w))));
        }
        md = fminf(md, __shfl_xor_sync(0xffffffffu, md, 1));
        md = fminf(md, __shfl_xor_sync(0xffffffffu, md, 2));
        if (part == 0) {
            float qsq = fmaf(qx, qx, fmaf(qy, qy, qz * qz));
            float mind = sqrtf(fmaxf(md + qsq, EPSD));
            float ls = fb2[0];
#pragma unroll
            for (int j = 0; j < 16; ++j) {
                float z = fmaf(fw1[3*j], qx, fmaf(fw1[3*j+1], qy, fmaf(fw1[3*j+2], qz, fb1[j])));
                float sp = fmaxf(z, 0.0f) + log1pf(expf(-fabsf(z)));
                ls = fmaf(fw2[j], sp, ls);
            }
            ls = fminf(fmaxf(ls, 0.0f), 5.0f);
            g_omega[qi] = OMEGA0 * (1.0f + ls * expf(-mind));
        }
        return;
    }
    {
        // ---- W hi/lo split ----
        int i = (b - XBLK - OBLK) * 256 + tid;
        float w = W[i];
        __nv_bfloat16 h = __float2bfloat16(w);
        g_Whi[i] = h;
        g_Wlo[i] = __float2bfloat16(w - __bfloat162float(h));
    }
}

// ---------------------------------------------------------------- GEMM + sin epilogue (pure async mainloop)
__global__ __launch_bounds__(256, 2)
void siren_gemm(const float* __restrict__ bias, float* __restrict__ out)
{
    extern __shared__ char sb[];
    const uint32_t sbase = smem_u32(sb);

    const int tid  = threadIdx.x;
    const int lane = tid & 31;
    const int wid  = tid >> 5;
    const int gRow0 = (blockIdx.x >> 1) * BM;
    const int gCol0 = (blockIdx.x & 1) * BN;

    const int warpM = (wid & 3) * 32;
    const int warpN = (wid >> 2) * 64;
    const int lr = lane >> 2;
    const int lc = (lane & 3) * 2;
    const int l7 = lane & 7, g = lane >> 3;
    const uint32_t aoff = (uint32_t)((warpM + l7 + (g & 1) * 8) * PITCH + ((g >> 1) & 1) * 16);
    const uint32_t boff = (uint32_t)((warpN + l7 + (g >> 1) * 8) * PITCH + (g & 1) * 16);

    // loader mapping: one 16B unit per buffer per thread
    const int r = tid >> 1, h = tid & 1;
    const __nv_bfloat16* srcAh = g_Xhi + (size_t)(gRow0 + r) * KDIM + h * 8;
    const __nv_bfloat16* srcAl = g_Xlo + (size_t)(gRow0 + r) * KDIM + h * 8;
    const __nv_bfloat16* srcBh = g_Whi + (size_t)(gCol0 + r) * KDIM + h * 8;
    const __nv_bfloat16* srcBl = g_Wlo + (size_t)(gCol0 + r) * KDIM + h * 8;
    const uint32_t dstOff = (uint32_t)(r * PITCH + h * 16);

    // prologue: chunks 0 and 1
#pragma unroll
    for (int c = 0; c < 2; ++c) {
        uint32_t st = sbase + c * STAGE + dstOff;
        cp16(st + OFF_AH, srcAh + c * BKC);
        cp16(st + OFF_AL, srcAl + c * BKC);
        cp16(st + OFF_BH, srcBh + c * BKC);
        cp16(st + OFF_BL, srcBl + c * BKC);
        CP_COMMIT();
    }

    float acc[2][8][4];
#pragma unroll
    for (int i = 0; i < 2; ++i)
#pragma unroll
        for (int j = 0; j < 8; ++j)
#pragma unroll
            for (int k = 0; k < 4; ++k) acc[i][j][k] = 0.0f;

    // ---- main loop: 16 chunks, 4 stages, prefetch distance 2 ----
#pragma unroll 1
    for (int c = 0; c < NCHUNK; ++c) {
        if (c + 2 < NCHUNK) {
            uint32_t st = sbase + ((c + 2) & 3) * STAGE + dstOff;
            cp16(st + OFF_AH, srcAh + (c + 2) * BKC);
            cp16(st + OFF_AL, srcAl + (c + 2) * BKC);
            cp16(st + OFF_BH, srcBh + (c + 2) * BKC);
            cp16(st + OFF_BL, srcBl + (c + 2) * BKC);
        }
        CP_COMMIT();          // empty group on tail iterations keeps counts aligned
        CP_WAIT2();
        __syncthreads();

        const uint32_t st = sbase + (c & 3) * STAGE;
        uint32_t ah[2][4], al[2][4], bq[4][4];
        const uint32_t ab = st + aoff;
        const uint32_t bb = st + boff;
        LDSM4(ah[0], ab + OFF_AH);
        LDSM4(ah[1], ab + OFF_AH + 16 * PITCH);
        LDSM4(al[0], ab + OFF_AL);
        LDSM4(al[1], ab + OFF_AL + 16 * PITCH);
#pragma unroll
        for (int p = 0; p < 4; ++p) LDSM4(bq[p], bb + OFF_BH + p * 16 * PITCH);
        // pass 1: hi*HI
#pragma unroll
        for (int mt = 0; mt < 2; ++mt)
#pragma unroll
            for (int p = 0; p < 4; ++p) {
                mma_bf16(acc[mt][2*p],   ah[mt], bq[p][0], bq[p][1]);
                mma_bf16(acc[mt][2*p+1], ah[mt], bq[p][2], bq[p][3]);
            }
        // pass 2: lo*HI
#pragma unroll
        for (int mt = 0; mt < 2; ++mt)
#pragma unroll
            for (int p = 0; p < 4; ++p) {
                mma_bf16(acc[mt][2*p],   al[mt], bq[p][0], bq[p][1]);
                mma_bf16(acc[mt][2*p+1], al[mt], bq[p][2], bq[p][3]);
            }
        // pass 3: hi*LO
#pragma unroll
        for (int p = 0; p < 4; ++p) LDSM4(bq[p], bb + OFF_BL + p * 16 * PITCH);
#pragma unroll
        for (int mt = 0; mt < 2; ++mt)
#pragma unroll
            for (int p = 0; p < 4; ++p) {
                mma_bf16(acc[mt][2*p],   ah[mt], bq[p][0], bq[p][1]);
                mma_bf16(acc[mt][2*p+1], ah[mt], bq[p][2], bq[p][3]);
            }
    }
    // NOTE: epilogue staging uses bytes [0, 67584) = stages 0..2 only; the last
    // chunk (15) was read from stage 3 [73728, 98304) — no overlap, and the
    // barrier in iteration 15 ordered all earlier-stage readers. Safe.

    // ---- epilogue: sin(omega*(acc+bias)) -> SMEM -> coalesced STG ----
    float* stg = (float*)sb;
#pragma unroll
    for (int mt = 0; mt < 2; ++mt) {
        int r0 = warpM + mt * 16 + lr;
        float o0 = __ldg(g_omega + gRow0 + r0);
        float o1 = __ldg(g_omega + gRow0 + r0 + 8);
#pragma unroll
        for (int nt = 0; nt < 8; ++nt) {
            int c0 = warpN + nt * 8 + lc;
            float b0 = __ldg(bias + gCol0 + c0), b1 = __ldg(bias + gCol0 + c0 + 1);
            float* a = acc[mt][nt];
            *(float2*)(stg + r0 * EPI_STRIDE + c0) =
                make_float2(__sinf(o0 * (a[0] + b0)), __sinf(o0 * (a[1] + b1)));
            *(float2*)(stg + (r0 + 8) * EPI_STRIDE + c0) =
                make_float2(__sinf(o1 * (a[2] + b0)), __sinf(o1 * (a[3] + b1)));
        }
    }
    __syncthreads();
#pragma unroll
    for (int i = 0; i < 16; ++i) {
        int lin = tid + i * 256;
        int rr = lin >> 5, c4 = (lin & 31) * 4;
        *(float4*)(out + (size_t)(gRow0 + rr) * ODIM + gCol0 + c4) =
            *(const float4*)(stg + rr * EPI_STRIDE + c4);
    }
}

// ---------------------------------------------------------------- launch
extern "C" void kernel_launch(void* const* d_in, const int* in_sizes, int n_in,
                              void* d_out, int out_size)
{
    const float* x     = (const float*)d_in[0];
    const float* q     = (const float*)d_in[1];
    const float* atoms = (const float*)d_in[2];
    const float* W     = (const float*)d_in[3];
    const float* bias  = (const float*)d_in[4];
    const float* fw1   = (const float*)d_in[5];
    const float* fb1   = (const float*)d_in[6];
    const float* fw2   = (const float*)d_in[7];
    const float* fb2   = (const float*)d_in[8];
    float* out = (float*)d_out;
    (void)in_sizes; (void)n_in; (void)out_size;

    cudaFuncSetAttribute(siren_gemm, cudaFuncAttributeMaxDynamicSharedMemorySize, SM_BYTES);

    prep_kernel<<<XBLK + OBLK + WBLK, 256>>>(x, W, q, atoms, fw1, fb1, fw2, fb2);
    siren_gemm<<<(NROWS / BM) * (ODIM / BN), 256, SM_BYTES>>>(bias, out);
}

// round 7
// speedup vs baseline: 2.3967x; 2.3967x over previous
#include <cuda_runtime.h>
#include <cuda_bf16.h>
#include <stdint.h>
#include <math.h>

// ---------------------------------------------------------------- constants
#define BATCH   2
#define NQ      16384
#define NATOMS  1024
#define KDIM    256
#define ODIM    256
#define NROWS   (BATCH * NQ)
#define OMEGA0  30.0f
#define EPSD    1e-4f

#define BM      128
#define BN      128
#define BKC     16
#define NCHUNK  (KDIM / BKC)     // 16

#define PITCH   48               // bf16 tile row pitch (conflict-free ldmatrix)
#define A_ST    12288            // per A stage: hi 6144 + lo 6144
#define B_ST    12288
#define X_ST    8192             // fp32 X chunk 128x16
#define OFF_A   0                // 3 stages -> 36864
#define OFF_B   36864            // 3 stages -> 73728
#define OFF_X   73728            // 4 stages -> 106496
#define OFF_ATOM (OFF_X + 2 * X_ST)   // overlaps X stages 2,3 (prologue only)
#define OFF_OMEGA 106496
#define OFF_PART  107008
#define SM_BYTES  108544
#define EPI_STRIDE 132           // epilogue staging pitch (floats)

static __device__ __nv_bfloat16 g_Whi[ODIM * KDIM];
static __device__ __nv_bfloat16 g_Wlo[ODIM * KDIM];
static __device__ float4        g_atom4[BATCH * NATOMS];

// ---------------------------------------------------------------- helpers
__device__ __forceinline__ uint32_t smem_u32(const void* p) {
    uint32_t a;
    asm("{ .reg .u64 t; cvta.to.shared.u64 t, %1; cvt.u32.u64 %0, t; }" : "=r"(a) : "l"(p));
    return a;
}
__device__ __forceinline__ uint32_t swz(uint32_t o) { return o ^ ((o >> 3) & 0x70); }
__device__ __forceinline__ void sts_u4(uint32_t a, uint32_t x, uint32_t y,
                                       uint32_t z, uint32_t w) {
    asm volatile("st.shared.v4.b32 [%0], {%1,%2,%3,%4};" :: "r"(a), "r"(x), "r"(y), "r"(z), "r"(w));
}
__device__ __forceinline__ void cp16(uint32_t dst, const void* src) {
    asm volatile("cp.async.cg.shared.global [%0], [%1], 16;" :: "r"(dst), "l"(src));
}
#define CP_COMMIT() asm volatile("cp.async.commit_group;")
#define CP_WAIT0()  asm volatile("cp.async.wait_group 0;")
#define CP_WAIT2()  asm volatile("cp.async.wait_group 2;")

#define LDSM4(r, a) \
    asm volatile("ldmatrix.sync.aligned.m8n8.x4.shared.b16 {%0,%1,%2,%3}, [%4];" \
        : "=r"((r)[0]), "=r"((r)[1]), "=r"((r)[2]), "=r"((r)[3]) : "r"(a))

__device__ __forceinline__ void mma_bf16(float* c, const uint32_t* a,
                                         uint32_t b0, uint32_t b1) {
    asm volatile(
        "mma.sync.aligned.m16n8k16.row.col.f32.bf16.bf16.f32 "
        "{%0,%1,%2,%3}, {%4,%5,%6,%7}, {%8,%9}, {%0,%1,%2,%3};"
        : "+f"(c[0]), "+f"(c[1]), "+f"(c[2]), "+f"(c[3])
        : "r"(a[0]), "r"(a[1]), "r"(a[2]), "r"(a[3]), "r"(b0), "r"(b1));
}
__device__ __forceinline__ uint2 split4(float4 v, uint2& lo) {
    __nv_bfloat16 hx = __float2bfloat16(v.x), hy = __float2bfloat16(v.y);
    __nv_bfloat16 hz = __float2bfloat16(v.z), hw = __float2bfloat16(v.w);
    uint2 hi;
    hi.x = (uint32_t)__bfloat16_as_ushort(hx) | ((uint32_t)__bfloat16_as_ushort(hy) << 16);
    hi.y = (uint32_t)__bfloat16_as_ushort(hz) | ((uint32_t)__bfloat16_as_ushort(hw) << 16);
    __nv_bfloat16 lx = __float2bfloat16(v.x - __bfloat162float(hx));
    __nv_bfloat16 ly = __float2bfloat16(v.y - __bfloat162float(hy));
    __nv_bfloat16 lz = __float2bfloat16(v.z - __bfloat162float(hz));
    __nv_bfloat16 lw = __float2bfloat16(v.w - __bfloat162float(hw));
    lo.x = (uint32_t)__bfloat16_as_ushort(lx) | ((uint32_t)__bfloat16_as_ushort(ly) << 16);
    lo.y = (uint32_t)__bfloat16_as_ushort(lz) | ((uint32_t)__bfloat16_as_ushort(lw) << 16);
    return hi;
}

// ---------------------------------------------------------------- prep: W split + atom pack
__global__ __launch_bounds__(256)
void prep_kernel(const float* __restrict__ W, const float* __restrict__ atoms)
{
    int b = blockIdx.x;
    if (b < (ODIM * KDIM) / 256) {
        int i = b * 256 + threadIdx.x;
        float w = W[i];
        __nv_bfloat16 h = __float2bfloat16(w);
        g_Whi[i] = h;
        g_Wlo[i] = __float2bfloat16(w - __bfloat162float(h));
    } else {
        int i = (b - (ODIM * KDIM) / 256) * 256 + threadIdx.x;
        float ax = atoms[i*3], ay = atoms[i*3+1], az = atoms[i*3+2];
        g_atom4[i] = make_float4(ax, ay, az, fmaf(ax, ax, fmaf(ay, ay, az*az)));
    }
}

// ---------------------------------------------------------------- fused kernel
__global__ __launch_bounds__(256, 2)
void siren_fused(const float* __restrict__ X, const float* __restrict__ Q,
                 const float* __restrict__ bias,
                 const float* __restrict__ fw1, const float* __restrict__ fb1,
                 const float* __restrict__ fw2, const float* __restrict__ fb2,
                 float* __restrict__ out)
{
    extern __shared__ char sb[];
    const uint32_t sbase = smem_u32(sb);

    const int tid  = threadIdx.x;
    const int lane = tid & 31;
    const int wid  = tid >> 5;
    const int gRow0 = (blockIdx.x >> 1) * BM;
    const int gCol0 = (blockIdx.x & 1) * BN;
    const int batch = (gRow0 >= NQ) ? 1 : 0;

    const int warpM = (wid & 3) * 32;
    const int warpN = (wid >> 2) * 64;
    const int lr = lane >> 2;
    const int lc = (lane & 3) * 2;
    const int l7 = lane & 7, g = lane >> 3;
    const uint32_t aoff = (uint32_t)((warpM + l7 + (g & 1) * 8) * PITCH + ((g >> 1) & 1) * 16);
    const uint32_t boff = (uint32_t)((warpN + l7 + (g >> 1) * 8) * PITCH + (g & 1) * 16);

    // ---- loaders ------------------------------------------------------
    auto prefB = [&](int c, int st) {
        int n = tid >> 1, q = tid & 1;
        uint32_t d = sbase + OFF_B + st * B_ST + n * PITCH + q * 16;
        const int gs = (gCol0 + n) * KDIM + c * BKC + q * 8;
        cp16(d, g_Whi + gs);
        cp16(d + 6144, g_Wlo + gs);
    };
    auto prefX = [&](int c) {
        uint32_t base = sbase + OFF_X + (uint32_t)(c & 3) * X_ST;
        const float* src = X + (size_t)gRow0 * KDIM + c * BKC;
#pragma unroll
        for (int i = 0; i < 2; ++i) {
            int u = tid + i * 256;
            cp16(base + swz((uint32_t)u * 16), src + (size_t)(u >> 2) * KDIM + (u & 3) * 4);
        }
    };
    auto convertX = [&](int c, int st) {
        const char* xs = sb + OFF_X + (c & 3) * X_ST;
        int r = tid >> 1, h = tid & 1;
        uint32_t o = (uint32_t)(r * 64 + h * 32);
        float4 v0 = *(const float4*)(xs + swz(o));
        float4 v1 = *(const float4*)(xs + swz(o + 16));
        uint2 l0, l1;
        uint2 h0 = split4(v0, l0), h1 = split4(v1, l1);
        uint32_t dst = sbase + OFF_A + (uint32_t)st * A_ST + r * PITCH + h * 16;
        sts_u4(dst,        h0.x, h0.y, h1.x, h1.y);
        sts_u4(dst + 6144, l0.x, l0.y, l1.x, l1.y);
    };

    // ---- prologue: one big group (B0,B1,X0,X1,atoms) ----
    prefB(0, 0);
    prefB(1, 1);
    prefX(0);
    prefX(1);
    {
        const float4* ap = g_atom4 + batch * NATOMS;
#pragma unroll
        for (int i = 0; i < 4; ++i) {
            int lin = tid + i * 256;
            cp16(sbase + OFF_ATOM + lin * 16, ap + lin);
        }
    }
    CP_COMMIT();
    CP_WAIT0();
    __syncthreads();

    // ---- omega min-dist scan (2 threads/query, 2 fmin chains) ----
    {
        const int qi = tid & 127, qq = tid >> 7;
        const float* qp = Q + (size_t)(gRow0 + qi) * 3;
        float qx = qp[0], qy = qp[1], qz = qp[2];
        float nqx = -2.f * qx, nqy = -2.f * qy, nqz = -2.f * qz;
        const float4* at = (const float4*)(sb + OFF_ATOM) + qq * 512;
        float m0 = 3.4e38f, m1 = 3.4e38f;
#pragma unroll 4
        for (int j = 0; j < 512; j += 2) {
            float4 a0 = at[j], a1 = at[j + 1];
            m0 = fminf(m0, fmaf(a0.x, nqx, fmaf(a0.y, nqy, fmaf(a0.z, nqz, a0.w))));
            m1 = fminf(m1, fmaf(a1.x, nqx, fmaf(a1.y, nqy, fmaf(a1.z, nqz, a1.w))));
        }
        ((float*)(sb + OFF_PART))[qq * 128 + qi] = fminf(m0, m1);
    }
    __syncthreads();            // partials visible; atom reads complete

    if (tid < 128) {
        const float* part = (const float*)(sb + OFF_PART);
        float m = fminf(part[tid], part[128 + tid]);
        const float* qp = Q + (size_t)(gRow0 + tid) * 3;
        float qx = qp[0], qy = qp[1], qz = qp[2];
        float qsq = fmaf(qx, qx, fmaf(qy, qy, qz * qz));
        float mind = sqrtf(fmaxf(m + qsq, EPSD));
        float ls = __ldg(fb2);
#pragma unroll
        for (int j = 0; j < 16; ++j) {
            float z = fmaf(__ldg(fw1 + 3*j), qx,
                      fmaf(__ldg(fw1 + 3*j + 1), qy,
                      fmaf(__ldg(fw1 + 3*j + 2), qz, __ldg(fb1 + j))));
            float sp = fmaxf(z, 0.0f) + log1pf(expf(-fabsf(z)));
            ls = fmaf(__ldg(fw2 + j), sp, ls);
        }
        ls = fminf(fmaxf(ls, 0.0f), 5.0f);
        ((float*)(sb + OFF_OMEGA))[tid] = OMEGA0 * (1.0f + ls * expf(-mind));
    }

    convertX(0, 0);             // A(0) ready (visible after iter-0 barrier)
    prefX(2);                   // stage 2 (atoms region now dead)
    CP_COMMIT();                // group P2

    float acc[2][8][4];
#pragma unroll
    for (int i = 0; i < 2; ++i)
#pragma unroll
        for (int j = 0; j < 8; ++j)
#pragma unroll
            for (int k = 0; k < 4; ++k) acc[i][j][k] = 0.0f;

    // ---- main loop: 16 chunks; A/B rings 3 stages; X ring 4 stages ----
    int stA = 0;                // (c % 3)
#pragma unroll 1
    for (int c = 0; c < NCHUNK; ++c) {
        const int stN1 = (stA == 2) ? 0 : stA + 1;   // (c+1)%3
        const int stN2 = (stN1 == 2) ? 0 : stN1 + 1; // (c+2)%3

        if (c + 3 < NCHUNK) prefX(c + 3);
        if (c + 2 < NCHUNK) prefB(c + 2, stN2);
        CP_COMMIT();
        CP_WAIT2();
        __syncthreads();

        const uint32_t ab = sbase + OFF_A + (uint32_t)stA * A_ST + aoff;
        const uint32_t bb = sbase + OFF_B + (uint32_t)stA * B_ST + boff;
        uint32_t ah[2][4], al[2][4], bq[4][4];
        LDSM4(ah[0], ab);
        LDSM4(ah[1], ab + 16 * PITCH);
        LDSM4(al[0], ab + 6144);
        LDSM4(al[1], ab + 6144 + 16 * PITCH);
#pragma unroll
        for (int p = 0; p < 4; ++p) LDSM4(bq[p], bb + p * 16 * PITCH);
        // pass 1: hi*HI
#pragma unroll
        for (int mt = 0; mt < 2; ++mt)
#pragma unroll
            for (int p = 0; p < 4; ++p) {
                mma_bf16(acc[mt][2*p],   ah[mt], bq[p][0], bq[p][1]);
                mma_bf16(acc[mt][2*p+1], ah[mt], bq[p][2], bq[p][3]);
            }
        // pass 2: lo*HI
#pragma unroll
        for (int mt = 0; mt < 2; ++mt)
#pragma unroll
            for (int p = 0; p < 4; ++p) {
                mma_bf16(acc[mt][2*p],   al[mt], bq[p][0], bq[p][1]);
                mma_bf16(acc[mt][2*p+1], al[mt], bq[p][2], bq[p][3]);
            }
        // pass 3: hi*LO
#pragma unroll
        for (int p = 0; p < 4; ++p) LDSM4(bq[p], bb + 6144 + p * 16 * PITCH);
#pragma unroll
        for (int mt = 0; mt < 2; ++mt)
#pragma unroll
            for (int p = 0; p < 4; ++p) {
                mma_bf16(acc[mt][2*p],   ah[mt], bq[p][0], bq[p][1]);
                mma_bf16(acc[mt][2*p+1], ah[mt], bq[p][2], bq[p][3]);
            }

        if (c + 1 < NCHUNK) convertX(c + 1, stN1);
        stA = stN1;
    }
    __syncthreads();            // ring reads done; smem free for epilogue

    // ---- epilogue: sin(omega*(acc+bias)) -> SMEM -> coalesced STG ----
    float* stg = (float*)sb;
    const float* omg = (const float*)(sb + OFF_OMEGA);
#pragma unroll
    for (int mt = 0; mt < 2; ++mt) {
        int r0 = warpM + mt * 16 + lr;
        float o0 = omg[r0], o1 = omg[r0 + 8];
#pragma unroll
        for (int nt = 0; nt < 8; ++nt) {
            int c0 = warpN + nt * 8 + lc;
            float b0 = __ldg(bias + gCol0 + c0), b1 = __ldg(bias + gCol0 + c0 + 1);
            float* a = acc[mt][nt];
            *(float2*)(stg + r0 * EPI_STRIDE + c0) =
                make_float2(__sinf(o0 * (a[0] + b0)), __sinf(o0 * (a[1] + b1)));
            *(float2*)(stg + (r0 + 8) * EPI_STRIDE + c0) =
                make_float2(__sinf(o1 * (a[2] + b0)), __sinf(o1 * (a[3] + b1)));
        }
    }
    __syncthreads();
#pragma unroll
    for (int i = 0; i < 16; ++i) {
        int lin = tid + i * 256;
        int rr = lin >> 5, c4 = (lin & 31) * 4;
        *(float4*)(out + (size_t)(gRow0 + rr) * ODIM + gCol0 + c4) =
            *(const float4*)(stg + rr * EPI_STRIDE + c4);
    }
}

// ---------------------------------------------------------------- launch
extern "C" void kernel_launch(void* const* d_in, const int* in_sizes, int n_in,
                              void* d_out, int out_size)
{
    const float* x     = (const float*)d_in[0];
    const float* q     = (const float*)d_in[1];
    const float* atoms = (const float*)d_in[2];
    const float* W     = (const float*)d_in[3];
    const float* bias  = (const float*)d_in[4];
    const float* fw1   = (const float*)d_in[5];
    const float* fb1   = (const float*)d_in[6];
    const float* fw2   = (const float*)d_in[7];
    const float* fb2   = (const float*)d_in[8];
    float* out = (float*)d_out;
    (void)in_sizes; (void)n_in; (void)out_size;

    cudaFuncSetAttribute(siren_fused, cudaFuncAttributeMaxDynamicSharedMemorySize, SM_BYTES);

    prep_kernel<<<(ODIM * KDIM) / 256 + (BATCH * NATOMS) / 256, 256>>>(W, atoms);
    siren_fused<<<(NROWS / BM) * (ODIM / BN), 256, SM_BYTES>>>(x, q, bias, fw1, fb1, fw2, fb2, out);
}